// round 17
// baseline (speedup 1.0000x reference)
#include <cuda_runtime.h>

// Fused depth-3 sliding-window path signature (Chen chunk factorization).
// Compressed scan state (21 kept level-3 comps, j<=k) + arithmetically
// indexed, divergence-free reconstruction of the other 15.
// B=256, L=2048, C=6, WIN=64, STRIDE=32 -> 63 windows / batch.
// Grid = 1792 blocks (batch = blk/7, group g = blk%7) x 64 threads.
//
// Scaled shuffle identity (S2=2s2, S3=6s3), verified:
//   3 s1[a] S2[b][c] = S3[a][b][c] + S3[b][a][c] + S3[b][c][a]
//  case A (i<=j, j>k): S3[i][j][k] = 3 s1[k]S2[i][j] - S3[k][i][j] - S3[i][k][j]
//  case B (i>j>k):     S3[i][j][k] = 3 s1[k]S2[i][j] - 3 s1[j]S2[k][i]
//                                    + S3[j][k][i] + S3[k][j][i] - S3[i][k][j]
// All reads hit the kept region (rows 7+x*6+y, x<=y) or s1/S2; writes hit
// rows with x>y only -> no intra-pass hazard.
//
// Index decode (no tables):
//  case A, r in [0,70): entries ordered j=1..5, k=0..j-1, i=0..j.
//    per-j count j*(j+1), cumulative {0,2,8,20,40,70}.
//  case B, rb in [0,20): ordered j=1..4, k=0..j-1, i=j+1..5.
//    per-j count j*(5-j), cumulative {0,4,10,16,20}.

namespace {

constexpr int BATCH   = 256;
constexpr int LEN     = 2048;
constexpr int CH      = 6;
constexpr int NW      = 63;
constexpr int GROUPS  = 7;
constexpr int THREADS = 64;
constexpr int NCHUNKL = 10;               // chunks per block (1 overlap)
constexpr int NWL     = 9;                // windows per block (7*9 = 63 exact)
constexpr int NDXL    = 320;              // staged increments per block
constexpr int SROWD2  = 331;              // float2 row stride (320+10 pad, odd)
constexpr int NLANE   = NCHUNKL * CH;     // 60 scan lanes
constexpr int SCOL    = 61;               // sig column stride
constexpr int SM_FLOATS = 43 * SCOL;      // 2623 >= max(3*331*2, 9*258=2322)
constexpr int NRECA   = 70 * NCHUNKL;     // 700 case-A entries
constexpr int NREC    = 90 * NCHUNKL;     // 900 total entries

__global__ __launch_bounds__(THREADS, 14)
void fused_kernel(const float* __restrict__ path, float* __restrict__ out) {
    __shared__ __align__(16) float sm[SM_FLOATS];
    float2* __restrict__ s_dx2 = reinterpret_cast<float2*>(sm); // [3][SROWD2]
    float*  __restrict__ s_sig = sm;                            // [43][SCOL]

    const int tid = threadIdx.x;
    const int b   = blockIdx.x / GROUPS;
    const int g   = blockIdx.x - b * GROUPS;
    const int l0  = g * (NWL * 32);                 // 288 * g
    const float2* __restrict__ rowv =
        reinterpret_cast<const float2*>(path + (long long)b * (LEN * CH));

    // ---- stage increments as float2 (zero-fill global l >= 2047) ----
    for (int idx = tid; idx < NDXL * 3; idx += THREADS) {
        const int l  = idx / 3;
        const int pr = idx - l * 3;
        float2 d2 = make_float2(0.0f, 0.0f);
        const int gl = l0 + l;
        if (gl < LEN - 1) {
            const float2 v0 = rowv[gl * 3 + pr];
            const float2 v1 = rowv[gl * 3 + 3 + pr];
            d2.x = v1.x - v0.x;
            d2.y = v1.y - v0.y;
        }
        s_dx2[pr * SROWD2 + l + (l >> 5)] = d2;
    }
    __syncthreads();

    const int mc = tid / CH;       // local chunk 0..9 (tid>=60: idle lanes)
    const int i  = tid - mc * CH;  // leading channel
    const bool scan_lane = (tid < NLANE);

    float s1 = 0.0f;
    float T2[6];                   // 3 * S2  (S2 = 2*s2)
    float K3[6][6];                // kept S3[i][j][k], j<=k only
#pragma unroll
    for (int j = 0; j < 6; ++j) {
        T2[j] = 0.0f;
#pragma unroll
        for (int k = j; k < 6; ++k) K3[j][k] = 0.0f;
    }

    if (scan_lane) {
        const int base = 33 * mc;
        const float* __restrict__ rowi = sm + 2 * (i >> 1) * SROWD2 + (i & 1);

#pragma unroll 4
        for (int t = 0; t < 32; ++t) {
            const int off = base + t;
            const float2 d01 = s_dx2[0 * SROWD2 + off];
            const float2 d23 = s_dx2[1 * SROWD2 + off];
            const float2 d45 = s_dx2[2 * SROWD2 + off];
            const float di = rowi[2 * off];

            const float a   = fmaf(3.0f, s1, di);          // di + 3 s1 (old s1)
            const float b23 = fmaf(6.0f, s1, 3.0f * di);   // 3*(di + 2 s1)

            const float d[6] = {d01.x, d01.y, d23.x, d23.y, d45.x, d45.y};

            float coef[6];                                  // uses old T2
#pragma unroll
            for (int j = 0; j < 6; ++j) coef[j] = fmaf(a, d[j], T2[j]);

#pragma unroll
            for (int j = 0; j < 6; ++j)
#pragma unroll
                for (int k = j; k < 6; ++k)                 // kept 21 only
                    K3[j][k] = fmaf(coef[j], d[k], K3[j][k]);

#pragma unroll
            for (int j = 0; j < 6; ++j) T2[j] = fmaf(b23, d[j], T2[j]);
            s1 += di;
        }
    }

    // ---- snapshot d_last for local window wl = mc (local l' = 32mc+63) ----
    float dc[6];
    {
        const int off = 33 * mc + 64;
        const bool cwn = (mc < NWL);
        float2 c01 = make_float2(0.0f, 0.0f), c23 = c01, c45 = c01;
        if (cwn) {
            c01 = s_dx2[0 * SROWD2 + off];
            c23 = s_dx2[1 * SROWD2 + off];
            c45 = s_dx2[2 * SROWD2 + off];
        }
        dc[0] = c01.x; dc[1] = c01.y; dc[2] = c23.x;
        dc[3] = c23.y; dc[4] = c45.x; dc[5] = c45.y;
    }
    __syncthreads();   // all dx reads done before s_sig overwrites

    // ---- publish s1, S2 = T2/3, and the 21 kept S3 components ----
    if (scan_lane) {
        s_sig[tid] = s1;
        const float third = 1.0f / 3.0f;
#pragma unroll
        for (int j = 0; j < 6; ++j) s_sig[(1 + j) * SCOL + tid] = T2[j] * third;
#pragma unroll
        for (int j = 0; j < 6; ++j)
#pragma unroll
            for (int k = j; k < 6; ++k)
                s_sig[(7 + j * 6 + k) * SCOL + tid] = K3[j][k];
    }
    __syncthreads();

    // ---- reconstruct the 15 per (chunk,i) -> 900 per block ----
    for (int e = tid; e < NREC; e += THREADS) {
        int m, ri, rj, rk;
        bool caseA;
        if (e < NRECA) {
            caseA = true;
            m = e / 70;
            const int r = e - m * 70;
            // j via cumulative {0,2,8,20,40,70}
            rj = 1 + (r >= 2) + (r >= 8) + (r >= 20) + (r >= 40);
            const int cum = (rj == 1) ? 0 : (rj == 2) ? 2 : (rj == 3) ? 8
                          : (rj == 4) ? 20 : 40;
            const int rr = r - cum;
            rk = rr / (rj + 1);
            ri = rr - rk * (rj + 1);
        } else {
            caseA = false;
            const int eb = e - NRECA;
            m = eb / 20;
            const int rb = eb - m * 20;
            // j via cumulative {0,4,10,16,20}
            rj = 1 + (rb >= 4) + (rb >= 10) + (rb >= 16);
            const int cum = (rj == 1) ? 0 : (rj == 2) ? 4 : (rj == 3) ? 10 : 16;
            const int rr = rb - cum;
            const int per = 5 - rj;
            rk = rr / per;
            ri = rj + 1 + (rr - rk * per);
        }
        const int c0 = m * CH;

        const float s1k  = s_sig[c0 + rk];
        const float S2ij = s_sig[(1 + rj) * SCOL + c0 + ri];
        float U;
        if (caseA) {
            // S3[i][j][k] = 3 s1[k]S2[i][j] - S3[k][i][j] - S3[i][k][j]
            U = 3.0f * s1k * S2ij
              - s_sig[(7 + ri * 6 + rj) * SCOL + c0 + rk]    // S3[rk][ri][rj]
              - s_sig[(7 + rk * 6 + rj) * SCOL + c0 + ri];   // S3[ri][rk][rj]
        } else {
            // S3[i][j][k] = 3 s1[k]S2[i][j] - 3 s1[j]S2[k][i]
            //               + S3[j][k][i] + S3[k][j][i] - S3[i][k][j]
            U = 3.0f * s1k * S2ij
              - 3.0f * s_sig[c0 + rj] * s_sig[(1 + ri) * SCOL + c0 + rk]
              + s_sig[(7 + rk * 6 + ri) * SCOL + c0 + rj]    // S3[rj][rk][ri]
              + s_sig[(7 + rj * 6 + ri) * SCOL + c0 + rk]    // S3[rk][rj][ri]
              - s_sig[(7 + rk * 6 + rj) * SCOL + c0 + ri];   // S3[ri][rk][rj]
        }
        s_sig[(7 + rj * 6 + rk) * SCOL + c0 + ri] = U;
    }
    __syncthreads();

    // ---- combine into registers: window w = 9g + mc ----
    const bool cw = (mc < NWL);

    float r1 = 0.0f, r2[6], r3[6][6];
    if (cw) {
        const int ca  = tid;               // A_w lane i
        const int cb0 = (mc + 1) * CH;     // A_{w+1} lane base
        const int cbi = cb0 + i;

        const float a1 = s_sig[ca];
        float b1[6];
#pragma unroll
        for (int j = 0; j < 6; ++j) b1[j] = s_sig[cb0 + j];

        const float m1 = a1 + b1[i];

        float A2r[6], M2[6];
#pragma unroll
        for (int j = 0; j < 6; ++j) {
            A2r[j] = s_sig[(1 + j) * SCOL + ca];
            M2[j]  = A2r[j] + s_sig[(1 + j) * SCOL + cbi] + 2.0f * a1 * b1[j];
        }

        r1 = m1 - dc[i];

        const float c2 = dc[i] - 2.0f * m1;
#pragma unroll
        for (int j = 0; j < 6; ++j) r2[j] = fmaf(c2, dc[j], M2[j]);

        const float t3a1 = 3.0f * a1;
        const float c3   = 3.0f * m1 - dc[i];
#pragma unroll
        for (int j = 0; j < 6; ++j) {
            const float a2b  = 3.0f * A2r[j];
            const float coef = fmaf(c3, dc[j], -3.0f * M2[j]);
#pragma unroll
            for (int k = 0; k < 6; ++k) {
                float v = s_sig[(7 + j * 6 + k) * SCOL + ca]
                        + s_sig[(7 + j * 6 + k) * SCOL + cbi];
                v = fmaf(a2b, b1[k], v);
                v = fmaf(t3a1, s_sig[(1 + k) * SCOL + cb0 + j], v);
                r3[j][k] = fmaf(coef, dc[k], v);
            }
        }
    }
    __syncthreads();   // all s_sig reads done before output staging overwrites

    // ---- stage output in smem as [wl][258] ----
    if (cw) {
        float* __restrict__ so = sm + mc * 258;
        so[i] = r1;
#pragma unroll
        for (int j = 0; j < 6; ++j) so[6 + i * 6 + j] = r2[j];
#pragma unroll
        for (int j = 0; j < 6; ++j)
#pragma unroll
            for (int k = 0; k < 6; ++k) so[42 + i * 36 + j * 6 + k] = r3[j][k];
    }
    __syncthreads();

    // ---- float2-coalesced copy to global (9*258 = 2322 floats = 1161 f2) ----
    constexpr int CNT2 = NWL * 258 / 2;  // 1161
    const float2* __restrict__ ssrc = reinterpret_cast<const float2*>(sm);
    float2* __restrict__ gout = reinterpret_cast<float2*>(
        out + ((long long)b * NW + NWL * g) * 258);
    for (int idx = tid; idx < CNT2; idx += THREADS) gout[idx] = ssrc[idx];
}

}  // namespace

extern "C" void kernel_launch(void* const* d_in, const int* in_sizes, int n_in,
                              void* d_out, int out_size) {
    const float* path = (const float*)d_in[0];
    float* out = (float*)d_out;
    fused_kernel<<<BATCH * GROUPS, THREADS>>>(path, out);
}